// round 2
// baseline (speedup 1.0000x reference)
#include <cuda_runtime.h>
#include <math.h>

#define SS 512
#define CC 384
#define HH 12
#define NPROJ 1152   // 192 qs + 192 ks + 192 vs + 144 qp + 144 kp + 288 vp
#define KD 28        // 16 scalar + 4 points * 3
#define VD 40        // 16 scalar + 8 points * 3
#define COMB 576     // 192 scalar_out + 288 pol + 96 norms

// ---------------- scratch (device globals; no allocation allowed) ----------
__device__ float g_Wc[CC * NPROJ];
__device__ float g_bc[NPROJ];
__device__ float g_proj[SS * NPROJ];
__device__ float g_Qc[HH * SS * KD];
__device__ float g_Kc[HH * SS * KD];
__device__ float g_Vc[HH * SS * VD];
__device__ float g_attn[HH * SS * SS];
__device__ float g_out40[HH * SS * VD];
__device__ float g_comb[SS * COMB];
__device__ float g_maskf[SS];

// ---------------- K-1: normalize valid_mask to float regardless of dtype ---
// If mask is int32 (harness promotes bool->int32), bytes at idx%4!=0 within
// the first 512 bytes are all zero. If it's 1-byte bool, ~50% of them are 1.
__global__ void norm_mask(const unsigned char* __restrict__ m) {
    __shared__ int flag;
    int t = threadIdx.x;              // 512 threads
    if (t == 0) flag = 0;
    __syncthreads();
    if ((t & 3) != 0 && m[t] != 0) atomicOr(&flag, 1);
    __syncthreads();
    float v;
    if (flag) {                        // 1-byte bool layout
        v = (m[t] != 0) ? 1.0f : 0.0f;
    } else {                           // int32 layout
        v = (((const int*)m)[t] != 0) ? 1.0f : 0.0f;
    }
    g_maskf[t] = v;
}

// ---------------- K0: pack 6 weight matrices + biases into one buffer ------
__global__ void pack_weights(const float* __restrict__ Wq_s, const float* __restrict__ Wk_s,
                             const float* __restrict__ Wv_s, const float* __restrict__ Wq_p,
                             const float* __restrict__ Wk_p, const float* __restrict__ Wv_p,
                             const float* __restrict__ bq_s, const float* __restrict__ bk_s,
                             const float* __restrict__ bv_s, const float* __restrict__ bq_p,
                             const float* __restrict__ bk_p, const float* __restrict__ bv_p) {
    int total = CC * NPROJ;
    for (int e = blockIdx.x * blockDim.x + threadIdx.x; e < total + NPROJ;
         e += gridDim.x * blockDim.x) {
        if (e < total) {
            int k = e / NPROJ, col = e % NPROJ;
            float v;
            if      (col < 192)  v = Wq_s[k * 192 + col];
            else if (col < 384)  v = Wk_s[k * 192 + (col - 192)];
            else if (col < 576)  v = Wv_s[k * 192 + (col - 384)];
            else if (col < 720)  v = Wq_p[k * 144 + (col - 576)];
            else if (col < 864)  v = Wk_p[k * 144 + (col - 720)];
            else                 v = Wv_p[k * 288 + (col - 864)];
            g_Wc[e] = v;
        } else {
            int col = e - total;
            float v;
            if      (col < 192)  v = bq_s[col];
            else if (col < 384)  v = bk_s[col - 192];
            else if (col < 576)  v = bv_s[col - 384];
            else if (col < 720)  v = bq_p[col - 576];
            else if (col < 864)  v = bk_p[col - 720];
            else                 v = bv_p[col - 864];
            g_bc[col] = v;
        }
    }
}

// ---------------- generic SGEMM: C[M,N] = A[M,K] @ W[K,N] + bias, row mask -
// Requires M%64==0, N%64==0, K%16==0 (holds for all call sites).
__global__ void gemm64(const float* __restrict__ A, const float* __restrict__ W,
                       const float* __restrict__ bias, float* __restrict__ Cmat,
                       int M, int N, int K, const float* __restrict__ mask) {
    __shared__ __align__(16) float As[16][64];
    __shared__ __align__(16) float Ws[16][64];
    int tid = threadIdx.x;
    int tx = tid & 15, ty = tid >> 4;
    int n0 = blockIdx.x * 64, m0 = blockIdx.y * 64;

    float acc[4][4] = {};
    for (int k0 = 0; k0 < K; k0 += 16) {
        #pragma unroll
        for (int l = 0; l < 4; ++l) {
            int e  = tid + l * 256;
            int kk = e & 15, m = e >> 4;
            As[kk][m] = A[(m0 + m) * K + k0 + kk];
            int n = e & 63, kk2 = e >> 6;
            Ws[kk2][n] = W[(k0 + kk2) * N + n0 + n];
        }
        __syncthreads();
        #pragma unroll
        for (int kk = 0; kk < 16; ++kk) {
            float4 a4 = *(const float4*)&As[kk][ty * 4];
            float4 b4 = *(const float4*)&Ws[kk][tx * 4];
            float av[4] = {a4.x, a4.y, a4.z, a4.w};
            float bv[4] = {b4.x, b4.y, b4.z, b4.w};
            #pragma unroll
            for (int i = 0; i < 4; ++i)
                #pragma unroll
                for (int j = 0; j < 4; ++j) acc[i][j] += av[i] * bv[j];
        }
        __syncthreads();
    }
    #pragma unroll
    for (int i = 0; i < 4; ++i) {
        int m = m0 + ty * 4 + i;
        float sc = mask ? mask[m] : 1.0f;
        #pragma unroll
        for (int j = 0; j < 4; ++j) {
            int n = n0 + tx * 4 + j;
            Cmat[m * N + n] = (acc[i][j] + bias[n]) * sc;
        }
    }
}

// ---------------- K2: rotate points to global frame, pack Q/K/V rows -------
__global__ void rotate_pack(const float* __restrict__ rot, const float* __restrict__ trans) {
    int idx = blockIdx.x * blockDim.x + threadIdx.x;
    if (idx >= SS * HH) return;
    int s = idx / HH, h = idx % HH;
    const float* R = rot + s * 9;          // row-major R[i][j] = R[i*3+j]
    float t0 = trans[s * 3 + 0], t1 = trans[s * 3 + 1], t2 = trans[s * 3 + 2];
    const float* pr = g_proj + s * NPROJ;
    float* q = g_Qc + (h * SS + s) * KD;
    float* k = g_Kc + (h * SS + s) * KD;
    float* v = g_Vc + (h * SS + s) * VD;
    #pragma unroll
    for (int d = 0; d < 16; ++d) {
        q[d] = pr[h * 16 + d];
        k[d] = pr[192 + h * 16 + d];
        v[d] = pr[384 + h * 16 + d];
    }
    #pragma unroll
    for (int p = 0; p < 4; ++p) {
        const float* qp = pr + 576 + (h * 4 + p) * 3;
        q[16 + p * 3 + 0] = R[0] * qp[0] + R[1] * qp[1] + R[2] * qp[2] + t0;
        q[16 + p * 3 + 1] = R[3] * qp[0] + R[4] * qp[1] + R[5] * qp[2] + t1;
        q[16 + p * 3 + 2] = R[6] * qp[0] + R[7] * qp[1] + R[8] * qp[2] + t2;
        const float* kp = pr + 720 + (h * 4 + p) * 3;
        k[16 + p * 3 + 0] = R[0] * kp[0] + R[1] * kp[1] + R[2] * kp[2] + t0;
        k[16 + p * 3 + 1] = R[3] * kp[0] + R[4] * kp[1] + R[5] * kp[2] + t1;
        k[16 + p * 3 + 2] = R[6] * kp[0] + R[7] * kp[1] + R[8] * kp[2] + t2;
    }
    #pragma unroll
    for (int p = 0; p < 8; ++p) {
        const float* vp = pr + 864 + (h * 8 + p) * 3;
        v[16 + p * 3 + 0] = R[0] * vp[0] + R[1] * vp[1] + R[2] * vp[2] + t0;
        v[16 + p * 3 + 1] = R[3] * vp[0] + R[4] * vp[1] + R[5] * vp[2] + t1;
        v[16 + p * 3 + 2] = R[6] * vp[0] + R[7] * vp[1] + R[8] * vp[2] + t2;
    }
}

// ---------------- K3: logits + softmax. block = (h, 8 queries) -------------
__global__ void attn_logits(const float* __restrict__ pw) {
    int h = blockIdx.y;
    int i0 = blockIdx.x * 8;
    __shared__ float qb[8][KD];
    __shared__ float spw[4];
    __shared__ float lg[8][SS];
    int tid = threadIdx.x;

    if (tid < 8 * KD) {
        int il = tid / KD, d = tid % KD;
        qb[il][d] = g_Qc[(h * SS + i0 + il) * KD + d];
    }
    if (tid >= 8 * KD && tid < 8 * KD + 4) {
        float x = pw[h * 4 + (tid - 8 * KD)];
        spw[tid - 8 * KD] = (x > 20.0f) ? x : log1pf(expf(x));
    }
    __syncthreads();

    #pragma unroll
    for (int c = 0; c < 2; ++c) {
        int j = c * 256 + tid;
        float kk[KD];
        #pragma unroll
        for (int d = 0; d < KD; ++d) kk[d] = g_Kc[(h * SS + j) * KD + d];
        bool vj = g_maskf[j] != 0.0f;
        #pragma unroll
        for (int il = 0; il < 8; ++il) {
            float dot = 0.0f;
            #pragma unroll
            for (int d = 0; d < 16; ++d) dot += qb[il][d] * kk[d];
            float pt = 0.0f;
            #pragma unroll
            for (int p = 0; p < 4; ++p) {
                float dx = qb[il][16 + 3 * p + 0] - kk[16 + 3 * p + 0];
                float dy = qb[il][16 + 3 * p + 1] - kk[16 + 3 * p + 1];
                float dz = qb[il][16 + 3 * p + 2] - kk[16 + 3 * p + 2];
                pt += spw[p] * (dx * dx + dy * dy + dz * dz);
            }
            float l = 0.25f * dot - 0.5f * pt;
            lg[il][j] = vj ? l : -10000.0f;
        }
    }
    __syncthreads();

    // warp w handles query row w
    int w = tid >> 5, lane = tid & 31;
    float m = -1e30f;
    for (int j = lane; j < SS; j += 32) m = fmaxf(m, lg[w][j]);
    #pragma unroll
    for (int o = 16; o; o >>= 1) m = fmaxf(m, __shfl_xor_sync(0xFFFFFFFFu, m, o));
    float sum = 0.0f;
    for (int j = lane; j < SS; j += 32) {
        float e = expf(lg[w][j] - m);
        lg[w][j] = e;
        sum += e;
    }
    #pragma unroll
    for (int o = 16; o; o >>= 1) sum += __shfl_xor_sync(0xFFFFFFFFu, sum, o);
    float inv = g_maskf[i0 + w] / sum;
    for (int j = lane; j < SS; j += 32)
        g_attn[(h * SS + i0 + w) * SS + j] = lg[w][j] * inv;
}

// ---------------- K4: out40[h,i,:] = attn[h,i,:] @ Vc[h,:,:] ----------------
__global__ void attn_apply() {
    int h = blockIdx.y, i0 = blockIdx.x * 32;
    __shared__ float at[32][64];
    __shared__ float vv[64][VD];
    int tid = threadIdx.x;
    int il = tid >> 3, dg = tid & 7;   // 32 queries x 8 dim-groups (5 dims each)
    float acc[5] = {};
    for (int j0 = 0; j0 < SS; j0 += 64) {
        #pragma unroll
        for (int l = 0; l < 8; ++l) {
            int e = tid + l * 256;
            at[e >> 6][e & 63] = g_attn[(h * SS + i0 + (e >> 6)) * SS + j0 + (e & 63)];
        }
        #pragma unroll
        for (int l = 0; l < 10; ++l) {
            int e = tid + l * 256;
            vv[e / VD][e % VD] = g_Vc[(h * SS + j0 + e / VD) * VD + (e % VD)];
        }
        __syncthreads();
        #pragma unroll 8
        for (int jj = 0; jj < 64; ++jj) {
            float a = at[il][jj];
            #pragma unroll
            for (int q = 0; q < 5; ++q) acc[q] += a * vv[jj][dg * 5 + q];
        }
        __syncthreads();
    }
    #pragma unroll
    for (int q = 0; q < 5; ++q)
        g_out40[(h * SS + i0 + il) * VD + dg * 5 + q] = acc[q];
}

// ---------------- K5: build combined = [scalar_out | pol | point_norm] -----
__global__ void build_combined(const float* __restrict__ rot, const float* __restrict__ trans) {
    const int NSC = SS * 192;   // scalar copies
    const int NPT = SS * 96;    // point tasks (s, h, p)
    int idx = blockIdx.x * blockDim.x + threadIdx.x;
    if (idx < NSC) {
        int s = idx / 192, c = idx % 192;
        int h = c >> 4, d = c & 15;
        g_comb[s * COMB + c] = g_out40[(h * SS + s) * VD + d];
    } else if (idx < NSC + NPT) {
        int r = idx - NSC;
        int s = r / 96, q = r % 96;
        int h = q >> 3, p = q & 7;
        const float* o = g_out40 + (h * SS + s) * VD + 16 + 3 * p;
        float v0 = o[0] - trans[s * 3 + 0];
        float v1 = o[1] - trans[s * 3 + 1];
        float v2 = o[2] - trans[s * 3 + 2];
        const float* R = rot + s * 9;
        // pol = R^T v
        float p0 = R[0] * v0 + R[3] * v1 + R[6] * v2;
        float p1 = R[1] * v0 + R[4] * v1 + R[7] * v2;
        float p2 = R[2] * v0 + R[5] * v1 + R[8] * v2;
        float* cb = g_comb + s * COMB;
        cb[192 + (h * 8 + p) * 3 + 0] = p0;
        cb[192 + (h * 8 + p) * 3 + 1] = p1;
        cb[192 + (h * 8 + p) * 3 + 2] = p2;
        cb[480 + h * 8 + p] = sqrtf(p0 * p0 + p1 * p1 + p2 * p2);
    }
}

// ---------------------------------------------------------------------------
extern "C" void kernel_launch(void* const* d_in, const int* in_sizes, int n_in,
                              void* d_out, int out_size) {
    const float* single = (const float*)d_in[0];
    const float* rot    = (const float*)d_in[1];
    const float* trans  = (const float*)d_in[2];
    const float* Wq_s = (const float*)d_in[3];  const float* bq_s = (const float*)d_in[4];
    const float* Wk_s = (const float*)d_in[5];  const float* bk_s = (const float*)d_in[6];
    const float* Wv_s = (const float*)d_in[7];  const float* bv_s = (const float*)d_in[8];
    const float* Wq_p = (const float*)d_in[9];  const float* bq_p = (const float*)d_in[10];
    const float* Wk_p = (const float*)d_in[11]; const float* bk_p = (const float*)d_in[12];
    const float* Wv_p = (const float*)d_in[13]; const float* bv_p = (const float*)d_in[14];
    const float* pw   = (const float*)d_in[15];
    const float* Wo   = (const float*)d_in[16];
    const float* bo   = (const float*)d_in[17];
    const unsigned char* mask = (const unsigned char*)d_in[18];
    float* out = (float*)d_out;

    float *pWc, *pbc, *pproj, *pcomb, *pmaskf;
    cudaGetSymbolAddress((void**)&pWc,    g_Wc);
    cudaGetSymbolAddress((void**)&pbc,    g_bc);
    cudaGetSymbolAddress((void**)&pproj,  g_proj);
    cudaGetSymbolAddress((void**)&pcomb,  g_comb);
    cudaGetSymbolAddress((void**)&pmaskf, g_maskf);

    // K-1: canonicalize mask (handles bool-as-int32 or bool-as-byte)
    norm_mask<<<1, SS>>>(mask);
    // K0: pack weights
    pack_weights<<<512, 256>>>(Wq_s, Wk_s, Wv_s, Wq_p, Wk_p, Wv_p,
                               bq_s, bk_s, bv_s, bq_p, bk_p, bv_p);
    // K1: all projections, proj[512][1152]
    gemm64<<<dim3(NPROJ / 64, SS / 64), 256>>>(single, pWc, pbc, pproj,
                                               SS, NPROJ, CC, (const float*)0);
    // K2: rotate + pack per-head Q/K/V rows
    rotate_pack<<<(SS * HH + 255) / 256, 256>>>(rot, trans);
    // K3: logits + softmax
    attn_logits<<<dim3(SS / 8, HH), 256>>>(pw);
    // K4: attn @ V
    attn_apply<<<dim3(SS / 32, HH), 256>>>();
    // K5: combined features
    build_combined<<<(SS * 192 + SS * 96 + 255) / 256, 256>>>(rot, trans);
    // K6: output projection + bias + query mask
    gemm64<<<dim3(CC / 64, SS / 64), 256>>>(pcomb, Wo, bo, out, SS, CC, COMB, pmaskf);
}

// round 3
// speedup vs baseline: 1.1331x; 1.1331x over previous
#include <cuda_runtime.h>
#include <math.h>

#define SS 512
#define CC 384
#define HH 12
#define NPROJ 1152   // 192 qs + 192 ks + 192 vs + 144 qp + 144 kp + 288 vp
#define KD 28        // 16 scalar + 4 points * 3
#define VD 40        // 16 scalar + 8 points * 3
#define COMB 576     // 192 scalar_out + 288 pol + 96 norms

// ---------------- scratch (device globals; no allocation allowed) ----------
__device__ float g_Wc[CC * NPROJ];
__device__ float g_bc[NPROJ];
__device__ float g_proj[SS * NPROJ];
__device__ float g_Qc[HH * SS * KD];
__device__ float g_Kc[HH * SS * KD];
__device__ float g_Vc[HH * SS * VD];
__device__ float g_attn[HH * SS * SS];
__device__ float g_out40[HH * SS * VD];
__device__ float g_comb[SS * COMB];
__device__ float g_maskf[SS];

// ---------------- K0: pack weights + biases; block 0 also canonicalizes mask
__global__ void pack_weights(const float* __restrict__ Wq_s, const float* __restrict__ Wk_s,
                             const float* __restrict__ Wv_s, const float* __restrict__ Wq_p,
                             const float* __restrict__ Wk_p, const float* __restrict__ Wv_p,
                             const float* __restrict__ bq_s, const float* __restrict__ bk_s,
                             const float* __restrict__ bv_s, const float* __restrict__ bq_p,
                             const float* __restrict__ bk_p, const float* __restrict__ bv_p,
                             const unsigned char* __restrict__ msk) {
    if (blockIdx.x == 0) {
        // mask dtype detection: int32 (bool promoted) has zero bytes at idx%4!=0
        // within the first 512 bytes; 1-byte bool has ~50% ones there.
        __shared__ int flag;
        int t = threadIdx.x;             // 256
        if (t == 0) flag = 0;
        __syncthreads();
        #pragma unroll
        for (int b = t; b < 512; b += 256)
            if ((b & 3) != 0 && msk[b] != 0) atomicOr(&flag, 1);
        __syncthreads();
        for (int i = t; i < SS; i += 256)
            g_maskf[i] = flag ? (msk[i] != 0 ? 1.0f : 0.0f)
                              : (((const int*)msk)[i] != 0 ? 1.0f : 0.0f);
    }
    int total = CC * NPROJ;
    for (int e = blockIdx.x * blockDim.x + threadIdx.x; e < total + NPROJ;
         e += gridDim.x * blockDim.x) {
        if (e < total) {
            int k = e / NPROJ, col = e % NPROJ;
            float v;
            if      (col < 192)  v = Wq_s[k * 192 + col];
            else if (col < 384)  v = Wk_s[k * 192 + (col - 192)];
            else if (col < 576)  v = Wv_s[k * 192 + (col - 384)];
            else if (col < 720)  v = Wq_p[k * 144 + (col - 576)];
            else if (col < 864)  v = Wk_p[k * 144 + (col - 720)];
            else                 v = Wv_p[k * 288 + (col - 864)];
            g_Wc[e] = v;
        } else {
            int col = e - total;
            float v;
            if      (col < 192)  v = bq_s[col];
            else if (col < 384)  v = bk_s[col - 192];
            else if (col < 576)  v = bv_s[col - 384];
            else if (col < 720)  v = bq_p[col - 576];
            else if (col < 864)  v = bk_p[col - 720];
            else                 v = bv_p[col - 864];
            g_bc[col] = v;
        }
    }
}

// ---------------- generic SGEMM: C[M,N] = A[M,K] @ W[K,N] + bias, row mask -
__global__ void gemm64(const float* __restrict__ A, const float* __restrict__ W,
                       const float* __restrict__ bias, float* __restrict__ Cmat,
                       int M, int N, int K, const float* __restrict__ mask) {
    __shared__ __align__(16) float As[16][64];
    __shared__ __align__(16) float Ws[16][64];
    int tid = threadIdx.x;
    int tx = tid & 15, ty = tid >> 4;
    int n0 = blockIdx.x * 64, m0 = blockIdx.y * 64;

    float acc[4][4] = {};
    for (int k0 = 0; k0 < K; k0 += 16) {
        #pragma unroll
        for (int l = 0; l < 4; ++l) {
            int e  = tid + l * 256;
            int kk = e & 15, m = e >> 4;
            As[kk][m] = A[(m0 + m) * K + k0 + kk];
            int n = e & 63, kk2 = e >> 6;
            Ws[kk2][n] = W[(k0 + kk2) * N + n0 + n];
        }
        __syncthreads();
        #pragma unroll
        for (int kk = 0; kk < 16; ++kk) {
            float4 a4 = *(const float4*)&As[kk][ty * 4];
            float4 b4 = *(const float4*)&Ws[kk][tx * 4];
            float av[4] = {a4.x, a4.y, a4.z, a4.w};
            float bv[4] = {b4.x, b4.y, b4.z, b4.w};
            #pragma unroll
            for (int i = 0; i < 4; ++i)
                #pragma unroll
                for (int j = 0; j < 4; ++j) acc[i][j] += av[i] * bv[j];
        }
        __syncthreads();
    }
    #pragma unroll
    for (int i = 0; i < 4; ++i) {
        int m = m0 + ty * 4 + i;
        float sc = mask ? mask[m] : 1.0f;
        #pragma unroll
        for (int j = 0; j < 4; ++j) {
            int n = n0 + tx * 4 + j;
            Cmat[m * N + n] = (acc[i][j] + bias[n]) * sc;
        }
    }
}

// ---------------- K2: rotate points to global frame, pack Q/K/V rows -------
// One block per residue s. Coalesced read of proj row; 192 point tasks.
__global__ void rotate_pack(const float* __restrict__ rot, const float* __restrict__ trans) {
    int s = blockIdx.x;
    int t = threadIdx.x;                 // 128 threads
    __shared__ float pts[576];           // proj[s][576..1152]
    __shared__ float Rs[9], ts_[3];
    if (t < 9) Rs[t] = rot[s * 9 + t];
    if (t >= 16 && t < 19) ts_[t - 16] = trans[s * 3 + (t - 16)];
    const float* pr = g_proj + s * NPROJ;

    // scalar channels: cols 0..576 -> q/k/v scalar slots (coalesced reads)
    #pragma unroll
    for (int e = t; e < 576; e += 128) {
        float v = pr[e];
        int seg = e / 192, r = e % 192;
        int h = r >> 4, d = r & 15;
        if      (seg == 0) g_Qc[(h * SS + s) * KD + d] = v;
        else if (seg == 1) g_Kc[(h * SS + s) * KD + d] = v;
        else               g_Vc[(h * SS + s) * VD + d] = v;
    }
    // stage point channels (coalesced)
    #pragma unroll
    for (int e = t; e < 576; e += 128) pts[e] = pr[576 + e];
    __syncthreads();

    // 192 point rotations: 48 q-points, 48 k-points, 96 v-points
    #pragma unroll
    for (int task = t; task < 192; task += 128) {
        const float* p;
        float* o;
        if (task < 48) {
            p = pts + task * 3;
            o = g_Qc + ((task >> 2) * SS + s) * KD + 16 + (task & 3) * 3;
        } else if (task < 96) {
            int q = task - 48;
            p = pts + 144 + q * 3;
            o = g_Kc + ((q >> 2) * SS + s) * KD + 16 + (q & 3) * 3;
        } else {
            int q = task - 96;
            p = pts + 288 + q * 3;
            o = g_Vc + ((q >> 3) * SS + s) * VD + 16 + (q & 7) * 3;
        }
        float x = p[0], y = p[1], z = p[2];
        o[0] = Rs[0] * x + Rs[1] * y + Rs[2] * z + ts_[0];
        o[1] = Rs[3] * x + Rs[4] * y + Rs[5] * z + ts_[1];
        o[2] = Rs[6] * x + Rs[7] * y + Rs[8] * z + ts_[2];
    }
}

// ---------------- K3: logits + softmax. block = (h, 8 queries) -------------
__global__ void attn_logits(const float* __restrict__ pw) {
    int h = blockIdx.y;
    int i0 = blockIdx.x * 8;
    __shared__ float qb[8][KD];
    __shared__ float spw[4];
    __shared__ float lg[8][SS];
    int tid = threadIdx.x;

    if (tid < 8 * KD) {
        int il = tid / KD, d = tid % KD;
        qb[il][d] = g_Qc[(h * SS + i0 + il) * KD + d];
    }
    if (tid >= 8 * KD && tid < 8 * KD + 4) {
        float x = pw[h * 4 + (tid - 8 * KD)];
        spw[tid - 8 * KD] = (x > 20.0f) ? x : log1pf(expf(x));
    }
    __syncthreads();

    #pragma unroll
    for (int c = 0; c < 2; ++c) {
        int j = c * 256 + tid;
        float kk[KD];
        #pragma unroll
        for (int d = 0; d < KD; ++d) kk[d] = g_Kc[(h * SS + j) * KD + d];
        bool vj = g_maskf[j] != 0.0f;
        #pragma unroll
        for (int il = 0; il < 8; ++il) {
            float dot = 0.0f;
            #pragma unroll
            for (int d = 0; d < 16; ++d) dot += qb[il][d] * kk[d];
            float pt = 0.0f;
            #pragma unroll
            for (int p = 0; p < 4; ++p) {
                float dx = qb[il][16 + 3 * p + 0] - kk[16 + 3 * p + 0];
                float dy = qb[il][16 + 3 * p + 1] - kk[16 + 3 * p + 1];
                float dz = qb[il][16 + 3 * p + 2] - kk[16 + 3 * p + 2];
                pt += spw[p] * (dx * dx + dy * dy + dz * dz);
            }
            float l = 0.25f * dot - 0.5f * pt;
            lg[il][j] = vj ? l : -10000.0f;
        }
    }
    __syncthreads();

    // warp w handles query row w
    int w = tid >> 5, lane = tid & 31;
    float m = -1e30f;
    for (int j = lane; j < SS; j += 32) m = fmaxf(m, lg[w][j]);
    #pragma unroll
    for (int o = 16; o; o >>= 1) m = fmaxf(m, __shfl_xor_sync(0xFFFFFFFFu, m, o));
    float sum = 0.0f;
    for (int j = lane; j < SS; j += 32) {
        float e = __expf(lg[w][j] - m);
        lg[w][j] = e;
        sum += e;
    }
    #pragma unroll
    for (int o = 16; o; o >>= 1) sum += __shfl_xor_sync(0xFFFFFFFFu, sum, o);
    float inv = g_maskf[i0 + w] / sum;
    for (int j = lane; j < SS; j += 32)
        g_attn[(h * SS + i0 + w) * SS + j] = lg[w][j] * inv;
}

// ---------------- K4: out40[h,i,:] = attn[h,i,:] @ Vc[h,:,:] ----------------
__global__ void attn_apply() {
    int h = blockIdx.y, i0 = blockIdx.x * 32;
    __shared__ float at[32][64];
    __shared__ float vv[64][VD];
    int tid = threadIdx.x;
    int il = tid >> 3, dg = tid & 7;   // 32 queries x 8 dim-groups (5 dims each)
    float acc[5] = {};
    for (int j0 = 0; j0 < SS; j0 += 64) {
        #pragma unroll
        for (int l = 0; l < 8; ++l) {
            int e = tid + l * 256;
            at[e >> 6][e & 63] = g_attn[(h * SS + i0 + (e >> 6)) * SS + j0 + (e & 63)];
        }
        #pragma unroll
        for (int l = 0; l < 10; ++l) {
            int e = tid + l * 256;
            vv[e / VD][e % VD] = g_Vc[(h * SS + j0 + e / VD) * VD + (e % VD)];
        }
        __syncthreads();
        #pragma unroll 8
        for (int jj = 0; jj < 64; ++jj) {
            float a = at[il][jj];
            #pragma unroll
            for (int q = 0; q < 5; ++q) acc[q] += a * vv[jj][dg * 5 + q];
        }
        __syncthreads();
    }
    #pragma unroll
    for (int q = 0; q < 5; ++q)
        g_out40[(h * SS + i0 + il) * VD + dg * 5 + q] = acc[q];
}

// ---------------- K5: build combined = [scalar_out | pol | point_norm] -----
__global__ void build_combined(const float* __restrict__ rot, const float* __restrict__ trans) {
    const int NSC = SS * 192;   // scalar copies
    const int NPT = SS * 96;    // point tasks (s, h, p)
    int idx = blockIdx.x * blockDim.x + threadIdx.x;
    if (idx < NSC) {
        int s = idx / 192, c = idx % 192;
        int h = c >> 4, d = c & 15;
        g_comb[s * COMB + c] = g_out40[(h * SS + s) * VD + d];
    } else if (idx < NSC + NPT) {
        int r = idx - NSC;
        int s = r / 96, q = r % 96;
        int h = q >> 3, p = q & 7;
        const float* o = g_out40 + (h * SS + s) * VD + 16 + 3 * p;
        float v0 = o[0] - trans[s * 3 + 0];
        float v1 = o[1] - trans[s * 3 + 1];
        float v2 = o[2] - trans[s * 3 + 2];
        const float* R = rot + s * 9;
        // pol = R^T v
        float p0 = R[0] * v0 + R[3] * v1 + R[6] * v2;
        float p1 = R[1] * v0 + R[4] * v1 + R[7] * v2;
        float p2 = R[2] * v0 + R[5] * v1 + R[8] * v2;
        float* cb = g_comb + s * COMB;
        cb[192 + (h * 8 + p) * 3 + 0] = p0;
        cb[192 + (h * 8 + p) * 3 + 1] = p1;
        cb[192 + (h * 8 + p) * 3 + 2] = p2;
        cb[480 + h * 8 + p] = sqrtf(p0 * p0 + p1 * p1 + p2 * p2);
    }
}

// ---------------------------------------------------------------------------
extern "C" void kernel_launch(void* const* d_in, const int* in_sizes, int n_in,
                              void* d_out, int out_size) {
    const float* single = (const float*)d_in[0];
    const float* rot    = (const float*)d_in[1];
    const float* trans  = (const float*)d_in[2];
    const float* Wq_s = (const float*)d_in[3];  const float* bq_s = (const float*)d_in[4];
    const float* Wk_s = (const float*)d_in[5];  const float* bk_s = (const float*)d_in[6];
    const float* Wv_s = (const float*)d_in[7];  const float* bv_s = (const float*)d_in[8];
    const float* Wq_p = (const float*)d_in[9];  const float* bq_p = (const float*)d_in[10];
    const float* Wk_p = (const float*)d_in[11]; const float* bk_p = (const float*)d_in[12];
    const float* Wv_p = (const float*)d_in[13]; const float* bv_p = (const float*)d_in[14];
    const float* pw   = (const float*)d_in[15];
    const float* Wo   = (const float*)d_in[16];
    const float* bo   = (const float*)d_in[17];
    const unsigned char* mask = (const unsigned char*)d_in[18];
    float* out = (float*)d_out;

    float *pWc, *pbc, *pproj, *pcomb, *pmaskf;
    cudaGetSymbolAddress((void**)&pWc,    g_Wc);
    cudaGetSymbolAddress((void**)&pbc,    g_bc);
    cudaGetSymbolAddress((void**)&pproj,  g_proj);
    cudaGetSymbolAddress((void**)&pcomb,  g_comb);
    cudaGetSymbolAddress((void**)&pmaskf, g_maskf);

    // K0: pack weights (+ mask canonicalization in block 0)
    pack_weights<<<512, 256>>>(Wq_s, Wk_s, Wv_s, Wq_p, Wk_p, Wv_p,
                               bq_s, bk_s, bv_s, bq_p, bk_p, bv_p, mask);
    // K1: all projections, proj[512][1152]
    gemm64<<<dim3(NPROJ / 64, SS / 64), 256>>>(single, pWc, pbc, pproj,
                                               SS, NPROJ, CC, (const float*)0);
    // K2: rotate + pack per-head Q/K/V rows (block per residue)
    rotate_pack<<<SS, 128>>>(rot, trans);
    // K3: logits + softmax
    attn_logits<<<dim3(SS / 8, HH), 256>>>(pw);
    // K4: attn @ V
    attn_apply<<<dim3(SS / 32, HH), 256>>>();
    // K5: combined features
    build_combined<<<(SS * 192 + SS * 96 + 255) / 256, 256>>>(rot, trans);
    // K6: output projection + bias + query mask
    gemm64<<<dim3(CC / 64, SS / 64), 256>>>(pcomb, Wo, bo, out, SS, CC, COMB, pmaskf);
}